// round 1
// baseline (speedup 1.0000x reference)
#include <cuda_runtime.h>
#include <math.h>

// Problem constants
constexpr int NNODE = 4096;
constexpr int FD    = 256;   // feature dim
constexpr int HD    = 256;   // hidden dim
constexpr int NK    = 3;     // K graphs
constexpr int G4    = 1024;  // 4*H gates
constexpr int NWRD  = 128;   // 4096/32 bit-words per row
constexpr int SIG_LO = 10;   // START
constexpr int SIG_HI = 253;  // F_DIM - END (exclusive)

constexpr int ZOFF = NNODE * FD;            // res_z_bar offset in out
constexpr int AOFF = ZOFF + NNODE * FD * NK; // adj offset in out

// ---------------- scratch (device globals; no allocation allowed) ----------
__device__ float g_ys  [NNODE * HD];
__device__ float g_gnn [NNODE * HD];
__device__ float g_gx  [NNODE * G4];
__device__ float g_gates[NNODE * G4];
__device__ float g_h   [NNODE * HD];
__device__ float g_c   [NNODE * HD];
__device__ float g_dsum[NNODE * FD];
__device__ float g_dinv[NK * NNODE];
__device__ unsigned g_bits[NK * NNODE * NWRD];

__device__ __forceinline__ float sigf(float x) { return 1.f / (1.f + expf(-x)); }

// ---------------- prep: degrees + bit-pack + adj -> float out --------------
// one block per row i, 256 threads (8 warps)
__global__ void prep_kernel(const int* __restrict__ adj, float* __restrict__ out_adj)
{
    int i = blockIdx.x;
    int t = threadIdx.x;
    int lane = t & 31, warp = t >> 5;
    int c0 = 0, c1 = 0, c2 = 0;
    for (int w = warp; w < NWRD; w += 8) {
        int j = w * 32 + lane;
        long base = ((long)i * NNODE + j) * 3;
        int a0 = adj[base], a1 = adj[base + 1], a2 = adj[base + 2];
        out_adj[base]     = (float)a0;
        out_adj[base + 1] = (float)a1;
        out_adj[base + 2] = (float)a2;
        unsigned m0 = __ballot_sync(0xffffffffu, a0 != 0);
        unsigned m1 = __ballot_sync(0xffffffffu, a1 != 0);
        unsigned m2 = __ballot_sync(0xffffffffu, a2 != 0);
        if (lane == 0) {
            g_bits[0 * NNODE * NWRD + i * NWRD + w] = m0;
            g_bits[1 * NNODE * NWRD + i * NWRD + w] = m1;
            g_bits[2 * NNODE * NWRD + i * NWRD + w] = m2;
            c0 += __popc(m0); c1 += __popc(m1); c2 += __popc(m2);
        }
    }
    __shared__ int sc[8][3];
    if (lane == 0) { sc[warp][0] = c0; sc[warp][1] = c1; sc[warp][2] = c2; }
    __syncthreads();
    if (t < 3) {
        int s = 0;
        #pragma unroll
        for (int w = 0; w < 8; w++) s += sc[w][t];
        // deg = count + 1 (self loop) ; always > 0
        g_dinv[t * NNODE + i] = rsqrtf((float)(s + 1));
    }
}

// ---------------- small GEMM 64x64x16 (256 thr, 4x4/thread) ----------------
// MODE 0: C = scale[m] * (A@B + bias1[n])           (NN, ys)
// MODE 3: fc epilogue: delta=tanh(acc+bias1), zbar + dsum (NT)
template <int MODE, bool TRANSB>
__global__ void gemm64(const float* __restrict__ A, const float* __restrict__ B,
                       int Kd, int Nn,
                       const float* __restrict__ bias1,
                       const float* __restrict__ scale,
                       float* __restrict__ Cout,
                       const float* __restrict__ xin,
                       float* __restrict__ zout,
                       float* __restrict__ dsum,
                       int kidx)
{
    __shared__ __align__(16) float As[16][68];
    __shared__ __align__(16) float Bs[16][68];
    int t = threadIdx.x;
    int m0 = blockIdx.y * 64, n0 = blockIdx.x * 64;
    int tx = t & 15, ty = t >> 4;
    float acc[4][4] = {};
    int li = t >> 2, lk = (t & 3) * 4;

    for (int kt = 0; kt < Kd; kt += 16) {
        float4 av = *(const float4*)&A[(m0 + li) * Kd + kt + lk];
        As[lk][li] = av.x; As[lk + 1][li] = av.y; As[lk + 2][li] = av.z; As[lk + 3][li] = av.w;
        if (TRANSB) {
            float4 bv = *(const float4*)&B[(n0 + li) * Kd + kt + lk];
            Bs[lk][li] = bv.x; Bs[lk + 1][li] = bv.y; Bs[lk + 2][li] = bv.z; Bs[lk + 3][li] = bv.w;
        } else {
            int bk = t >> 4, bj = (t & 15) * 4;
            float4 bv = *(const float4*)&B[(kt + bk) * Nn + n0 + bj];
            *(float4*)&Bs[bk][bj] = bv;
        }
        __syncthreads();
        #pragma unroll
        for (int kk = 0; kk < 16; kk++) {
            float4 a4 = *(const float4*)&As[kk][ty * 4];
            float4 b4 = *(const float4*)&Bs[kk][tx * 4];
            float aa[4] = {a4.x, a4.y, a4.z, a4.w};
            float bb[4] = {b4.x, b4.y, b4.z, b4.w};
            #pragma unroll
            for (int r = 0; r < 4; r++)
                #pragma unroll
                for (int c = 0; c < 4; c++)
                    acc[r][c] = fmaf(aa[r], bb[c], acc[r][c]);
        }
        __syncthreads();
    }

    #pragma unroll
    for (int r = 0; r < 4; r++) {
        int m = m0 + ty * 4 + r;
        #pragma unroll
        for (int c = 0; c < 4; c++) {
            int n = n0 + tx * 4 + c;
            float v = acc[r][c];
            if (MODE == 0) {
                Cout[m * Nn + n] = scale[m] * (v + bias1[n]);
            } else { // MODE 3: fc epilogue
                float d = tanhf(v + bias1[n]);
                float z = xin[m * FD + n] + d;
                if (n >= SIG_LO && n < SIG_HI) z = sigf(z);
                zout[(m * FD + n) * NK + kidx] = z;
                if (kidx == 0) dsum[m * FD + n] = d;
                else           dsum[m * FD + n] += d;
            }
        }
    }
}

// ---------------- big GEMM 128x128x8 NT (256 thr, 8x8/thread) --------------
// MODE 1: C = A@B^T + bias1[n] + bias2[n]   (gx)
// MODE 2: C = A@B^T + addmat[m,n]           (lstm gates)
template <int MODE>
__global__ void gemm128(const float* __restrict__ A, const float* __restrict__ B,
                        int Kd, int Nn,
                        const float* __restrict__ bias1, const float* __restrict__ bias2,
                        const float* __restrict__ addmat, float* __restrict__ Cout)
{
    __shared__ __align__(16) float As[8][132];
    __shared__ __align__(16) float Bs[8][132];
    int t = threadIdx.x;
    int m0 = blockIdx.y * 128, n0 = blockIdx.x * 128;
    int tx = t & 15, ty = t >> 4;
    float acc[8][8] = {};
    int li = t >> 1, lk = (t & 1) * 4;

    for (int kt = 0; kt < Kd; kt += 8) {
        float4 av = *(const float4*)&A[(m0 + li) * Kd + kt + lk];
        As[lk][li] = av.x; As[lk + 1][li] = av.y; As[lk + 2][li] = av.z; As[lk + 3][li] = av.w;
        float4 bv = *(const float4*)&B[(n0 + li) * Kd + kt + lk];
        Bs[lk][li] = bv.x; Bs[lk + 1][li] = bv.y; Bs[lk + 2][li] = bv.z; Bs[lk + 3][li] = bv.w;
        __syncthreads();
        #pragma unroll
        for (int kk = 0; kk < 8; kk++) {
            float a[8], b[8];
            *(float4*)&a[0] = *(const float4*)&As[kk][ty * 8];
            *(float4*)&a[4] = *(const float4*)&As[kk][ty * 8 + 4];
            *(float4*)&b[0] = *(const float4*)&Bs[kk][tx * 8];
            *(float4*)&b[4] = *(const float4*)&Bs[kk][tx * 8 + 4];
            #pragma unroll
            for (int r = 0; r < 8; r++)
                #pragma unroll
                for (int c = 0; c < 8; c++)
                    acc[r][c] = fmaf(a[r], b[c], acc[r][c]);
        }
        __syncthreads();
    }

    #pragma unroll
    for (int r = 0; r < 8; r++) {
        int m = m0 + ty * 8 + r;
        #pragma unroll
        for (int c = 0; c < 8; c++) {
            int n = n0 + tx * 8 + c;
            float v = acc[r][c];
            if (MODE == 1) v += bias1[n] + bias2[n];
            else           v += addmat[m * Nn + n];
            Cout[m * Nn + n] = v;
        }
    }
}

// ---------------- SpMM: out[i,:] = dinv[i] * (sum_{bit(i,j)} ys[j,:] + ys[i,:])
// block: 64 rows x 64 cols, j-tiles of 128, 256 threads (4x4 acc)
__global__ void spmm_kernel(const float* __restrict__ ys, float* __restrict__ outm,
                            const unsigned* __restrict__ bits, const float* __restrict__ dinv)
{
    __shared__ __align__(16) float ys_s[128][64];
    __shared__ unsigned bw[64][4];
    int t = threadIdx.x;
    int c0 = blockIdx.x * 64, i0 = blockIdx.y * 64;
    int tx = t & 15, ty = t >> 4;
    float acc[4][4] = {};

    for (int jt = 0; jt < NNODE; jt += 128) {
        #pragma unroll
        for (int u = 0; u < 8; u++) {
            int idx = t + u * 256;           // 0..2047
            int j = idx >> 4, cc = (idx & 15) * 4;
            *(float4*)&ys_s[j][cc] = *(const float4*)&ys[(jt + j) * HD + c0 + cc];
        }
        {
            int row = t >> 2, q = t & 3;
            bw[row][q] = bits[(i0 + row) * NWRD + (jt >> 5) + q];
        }
        __syncthreads();

        for (int q = 0; q < 4; q++) {
            unsigned w0 = bw[ty * 4 + 0][q];
            unsigned w1 = bw[ty * 4 + 1][q];
            unsigned w2 = bw[ty * 4 + 2][q];
            unsigned w3 = bw[ty * 4 + 3][q];
            #pragma unroll 8
            for (int b = 0; b < 32; b++) {
                int jj = q * 32 + b;
                float4 v = *(const float4*)&ys_s[jj][tx * 4];
                if ((w0 >> b) & 1u) { acc[0][0] += v.x; acc[0][1] += v.y; acc[0][2] += v.z; acc[0][3] += v.w; }
                if ((w1 >> b) & 1u) { acc[1][0] += v.x; acc[1][1] += v.y; acc[1][2] += v.z; acc[1][3] += v.w; }
                if ((w2 >> b) & 1u) { acc[2][0] += v.x; acc[2][1] += v.y; acc[2][2] += v.z; acc[2][3] += v.w; }
                if ((w3 >> b) & 1u) { acc[3][0] += v.x; acc[3][1] += v.y; acc[3][2] += v.z; acc[3][3] += v.w; }
            }
        }
        __syncthreads();
    }

    #pragma unroll
    for (int rr = 0; rr < 4; rr++) {
        int i = i0 + ty * 4 + rr;
        float di = dinv[i];
        float4 s = *(const float4*)&ys[i * HD + c0 + tx * 4];  // self loop term
        float4 o;
        o.x = di * (acc[rr][0] + s.x);
        o.y = di * (acc[rr][1] + s.y);
        o.z = di * (acc[rr][2] + s.z);
        o.w = di * (acc[rr][3] + s.w);
        *(float4*)&outm[i * HD + c0 + tx * 4] = o;
    }
}

// ---------------- LSTM elementwise gate update -----------------------------
__global__ void lstm_elem(const float* __restrict__ gates, float* __restrict__ h,
                          float* __restrict__ c, int first)
{
    int idx = blockIdx.x * 256 + threadIdx.x;     // N*HD elems
    int n = idx >> 8, hh = idx & 255;
    int base = n * G4 + hh;
    float gi = gates[base];
    float gf = gates[base + 256];
    float gg = gates[base + 512];
    float go = gates[base + 768];
    float cp = first ? 0.f : c[idx];
    float cn = sigf(gf) * cp + sigf(gi) * tanhf(gg);
    c[idx] = cn;
    h[idx] = sigf(go) * tanhf(cn);
}

// ---------------- final prediction -----------------------------------------
__global__ void final_kernel(const float* __restrict__ x, float* __restrict__ out)
{
    int idx = blockIdx.x * 256 + threadIdx.x;     // N*FD elems
    int f = idx & 255;
    float z = x[idx] + g_dsum[idx] * (1.f / 3.f);
    if (f >= SIG_LO && f < SIG_HI) z = sigf(z);
    out[idx] = z;
}

// ---------------- launcher ---------------------------------------------------
extern "C" void kernel_launch(void* const* d_in, const int* in_sizes, int n_in,
                              void* d_out, int out_size)
{
    (void)in_sizes; (void)n_in; (void)out_size;
    const float* x     = (const float*)d_in[0];
    const float* gnn_w = (const float*)d_in[1];
    const float* gnn_b = (const float*)d_in[2];
    const float* w_ih  = (const float*)d_in[3];
    const float* w_hh  = (const float*)d_in[4];
    const float* b_ih  = (const float*)d_in[5];
    const float* b_hh  = (const float*)d_in[6];
    const float* fc_w  = (const float*)d_in[7];
    const float* fc_b  = (const float*)d_in[8];
    const int*   adj   = (const int*)d_in[9];
    float* out = (float*)d_out;

    float *p_ys, *p_gnn, *p_gx, *p_gates, *p_h, *p_c, *p_dsum, *p_dinv;
    unsigned* p_bits;
    cudaGetSymbolAddress((void**)&p_ys,   g_ys);
    cudaGetSymbolAddress((void**)&p_gnn,  g_gnn);
    cudaGetSymbolAddress((void**)&p_gx,   g_gx);
    cudaGetSymbolAddress((void**)&p_gates,g_gates);
    cudaGetSymbolAddress((void**)&p_h,    g_h);
    cudaGetSymbolAddress((void**)&p_c,    g_c);
    cudaGetSymbolAddress((void**)&p_dsum, g_dsum);
    cudaGetSymbolAddress((void**)&p_dinv, g_dinv);
    cudaGetSymbolAddress((void**)&p_bits, g_bits);

    // adj pass: degrees + bitmasks + adj->float copy into out
    prep_kernel<<<NNODE, 256>>>(adj, out + AOFF);

    for (int k = 0; k < NK; k++) {
        const float* dinvk = p_dinv + k * NNODE;
        const unsigned* bitsk = p_bits + (size_t)k * NNODE * NWRD;

        // ys[j,:] = dinv[j] * (x[j]@gnn_w[k] + gnn_b[k])
        gemm64<0, false><<<dim3(HD / 64, NNODE / 64), 256>>>(
            x, gnn_w + k * FD * HD, FD, HD,
            gnn_b + k * HD, dinvk, p_ys, nullptr, nullptr, nullptr, k);

        // gnn_out = dinv .* (A_bits @ ys + ys)
        spmm_kernel<<<dim3(HD / 64, NNODE / 64), 256>>>(p_ys, p_gnn, bitsk, dinvk);

        // gx = gnn_out @ w_ih^T + b_ih + b_hh   [N, 1024]
        gemm128<1><<<dim3(G4 / 128, NNODE / 128), 256>>>(
            p_gnn, w_ih + k * G4 * HD, HD, G4,
            b_ih + k * G4, b_hh + k * G4, nullptr, p_gx);

        // LSTM step 1 (h=c=0): gates == gx
        lstm_elem<<<NNODE * HD / 256, 256>>>(p_gx, p_h, p_c, 1);

        // LSTM steps 2..5
        for (int step = 1; step < 5; step++) {
            gemm128<2><<<dim3(G4 / 128, NNODE / 128), 256>>>(
                p_h, w_hh + k * G4 * HD, HD, G4,
                nullptr, nullptr, p_gx, p_gates);
            lstm_elem<<<NNODE * HD / 256, 256>>>(p_gates, p_h, p_c, 0);
        }

        // delta/fc + zbar + dsum accumulation (NT)
        gemm64<3, true><<<dim3(FD / 64, NNODE / 64), 256>>>(
            p_h, fc_w + k * FD * HD, HD, FD,
            fc_b + k * FD, nullptr, nullptr, x, out + ZOFF, p_dsum, k);
    }

    // pred = sig_slice(x + mean(deltas))
    final_kernel<<<NNODE * FD / 256, 256>>>(x, out);
}

// round 3
// speedup vs baseline: 2.5574x; 2.5574x over previous
#include <cuda_runtime.h>
#include <math.h>
#include <stdint.h>

// ---------------- problem constants ----------------
constexpr int NNODE = 4096;
constexpr int FD    = 256;
constexpr int HD    = 256;
constexpr int NK    = 3;
constexpr int G4    = 1024;
constexpr int NWRD  = 128;          // 4096/32
constexpr int SIG_LO = 10;
constexpr int SIG_HI = 253;
constexpr int NM = NNODE * FD;      // 2^20
constexpr int NG = NNODE * G4;
constexpr int ZOFF = NM;
constexpr int AOFF = ZOFF + NM * NK;

// ---------------- scratch (device globals) ----------------
__device__ float g_ys  [NK * NM];
__device__ float g_ysT [NK * NM];
__device__ float g_gnn [NK * NM];
__device__ float g_gx  [NK * NG];
__device__ float g_gates[NK * NG];
__device__ float g_h   [NK * NM];
__device__ float g_c   [NK * NM];
__device__ float g_delta[NK * NM];
__device__ float g_gwt [NK * FD * HD];
__device__ float g_dinv[NK * NNODE];
__device__ unsigned g_bits[NK * NNODE * NWRD];

__device__ __forceinline__ float sigf(float x) { return 1.f / (1.f + expf(-x)); }

// m16n8k8 tf32 mma (fp32 bits passed as tf32; fp32 accumulate)
__device__ __forceinline__ void mma8(float* c, const uint32_t* a, uint32_t b0, uint32_t b1) {
    asm volatile(
        "mma.sync.aligned.m16n8k8.row.col.f32.tf32.tf32.f32 "
        "{%0,%1,%2,%3}, {%4,%5,%6,%7}, {%8,%9}, {%0,%1,%2,%3};"
        : "+f"(c[0]), "+f"(c[1]), "+f"(c[2]), "+f"(c[3])
        : "r"(a[0]), "r"(a[1]), "r"(a[2]), "r"(a[3]), "r"(b0), "r"(b1));
}

// ---------------- prep: degrees + bit-pack + adj -> float out --------------
__global__ void prep_kernel(const int* __restrict__ adj, float* __restrict__ out_adj)
{
    int i = blockIdx.x;
    int t = threadIdx.x;
    int lane = t & 31, warp = t >> 5;
    int c0 = 0, c1 = 0, c2 = 0;
    for (int w = warp; w < NWRD; w += 8) {
        int j = w * 32 + lane;
        long base = ((long)i * NNODE + j) * 3;
        int a0 = adj[base], a1 = adj[base + 1], a2 = adj[base + 2];
        out_adj[base]     = (float)a0;
        out_adj[base + 1] = (float)a1;
        out_adj[base + 2] = (float)a2;
        unsigned m0 = __ballot_sync(0xffffffffu, a0 != 0);
        unsigned m1 = __ballot_sync(0xffffffffu, a1 != 0);
        unsigned m2 = __ballot_sync(0xffffffffu, a2 != 0);
        if (lane == 0) {
            g_bits[0 * NNODE * NWRD + i * NWRD + w] = m0;
            g_bits[1 * NNODE * NWRD + i * NWRD + w] = m1;
            g_bits[2 * NNODE * NWRD + i * NWRD + w] = m2;
            c0 += __popc(m0); c1 += __popc(m1); c2 += __popc(m2);
        }
    }
    __shared__ int sc[8][3];
    if (lane == 0) { sc[warp][0] = c0; sc[warp][1] = c1; sc[warp][2] = c2; }
    __syncthreads();
    if (t < 3) {
        int s = 0;
        #pragma unroll
        for (int w = 0; w < 8; w++) s += sc[w][t];
        g_dinv[t * NNODE + i] = rsqrtf((float)(s + 1));
    }
}

// ---------------- transpose gnn_w [K][F][H] -> g_gwt [K][H][F] --------------
__global__ void transpose_w(const float* __restrict__ w)
{
    __shared__ float t[32][33];
    int k = blockIdx.z;
    int f0 = blockIdx.y * 32, h0 = blockIdx.x * 32;
    int tx = threadIdx.x, ty = threadIdx.y;
    for (int i = ty; i < 32; i += 8)
        t[i][tx] = w[k * 65536 + (f0 + i) * 256 + h0 + tx];
    __syncthreads();
    for (int i = ty; i < 32; i += 8)
        g_gwt[k * 65536 + (h0 + i) * 256 + f0 + tx] = t[tx][i];
}

// ---------------- tf32 mma.sync GEMM: BM=128, BN=128, BK=32, K=256 ----------
// All operands NT: A[m][256], B[n][256]; C = A @ B^T (+ epilogue)
// EPI 0: ys = dinv[m]*(acc + gnn_b[n]) -> g_ys and g_ysT        (A=x, B=g_gwt)
// EPI 1: gx = acc + b_ih[n] + b_hh[n]  -> g_gx                  (A=g_gnn, B=w_ih)
// EPI 2: gates = acc + g_gx[m,n]       -> g_gates               (A=g_h, B=w_hh)
// EPI 3: d = tanh(acc+fc_b[n]); g_delta; zbar->out              (A=g_h, B=fc_w)
template <int EPI>
__global__ void __launch_bounds__(256, 2) gemm_mma(
    const float* __restrict__ Aext, const float* __restrict__ Bext,
    const float* __restrict__ b1,   const float* __restrict__ b2,
    const float* __restrict__ xin,  float* __restrict__ outp)
{
    constexpr int NOUT = (EPI == 1 || EPI == 2) ? G4 : 256;
    __shared__ float As[128][36];
    __shared__ float Bs[128][36];

    int tid = threadIdx.x;
    int lane = tid & 31, wid = tid >> 5;
    int wm = wid & 3, wn = wid >> 2;       // warps 4 x 2
    int g = lane >> 2, t = lane & 3;
    int k = blockIdx.z;
    int m0 = blockIdx.y * 128, n0 = blockIdx.x * 128;

    const float* Ab;
    if (EPI == 0)      Ab = Aext + m0 * 256;
    else if (EPI == 1) Ab = g_gnn + k * NM + m0 * 256;
    else               Ab = g_h   + k * NM + m0 * 256;
    const float* Bb;
    if (EPI == 0)      Bb = g_gwt + k * 65536 + n0 * 256;
    else if (EPI == 3) Bb = Bext + k * 65536 + n0 * 256;
    else               Bb = Bext + k * G4 * HD + n0 * 256;

    float acc[2][8][4] = {};

    for (int kt = 0; kt < 256; kt += 32) {
        #pragma unroll
        for (int u = 0; u < 4; u++) {
            int idx = tid + u * 256;
            int row = idx >> 3, c4 = (idx & 7) << 2;
            *(float4*)&As[row][c4] = *(const float4*)(Ab + row * 256 + kt + c4);
        }
        #pragma unroll
        for (int u = 0; u < 4; u++) {
            int idx = tid + u * 256;
            int row = idx >> 3, c4 = (idx & 7) << 2;
            *(float4*)&Bs[row][c4] = *(const float4*)(Bb + row * 256 + kt + c4);
        }
        __syncthreads();
        #pragma unroll
        for (int kk = 0; kk < 4; kk++) {
            int k0 = kk * 8;
            uint32_t af[2][4];
            #pragma unroll
            for (int mt = 0; mt < 2; mt++) {
                int r = wm * 32 + mt * 16 + g;
                af[mt][0] = __float_as_uint(As[r][k0 + t]);
                af[mt][1] = __float_as_uint(As[r + 8][k0 + t]);
                af[mt][2] = __float_as_uint(As[r][k0 + t + 4]);
                af[mt][3] = __float_as_uint(As[r + 8][k0 + t + 4]);
            }
            #pragma unroll
            for (int nt = 0; nt < 8; nt++) {
                int cN = wn * 64 + nt * 8 + g;
                uint32_t b0 = __float_as_uint(Bs[cN][k0 + t]);
                uint32_t b1v = __float_as_uint(Bs[cN][k0 + t + 4]);
                mma8(acc[0][nt], af[0], b0, b1v);
                mma8(acc[1][nt], af[1], b0, b1v);
            }
        }
        __syncthreads();
    }

    // epilogue: element (mA(+8), nA(+1))
    #pragma unroll
    for (int mt = 0; mt < 2; mt++) {
        #pragma unroll
        for (int nt = 0; nt < 8; nt++) {
            int mA = m0 + wm * 32 + mt * 16 + g;
            int nA = n0 + wn * 64 + nt * 8 + 2 * t;
            float* a4 = acc[mt][nt];
            #pragma unroll
            for (int hrow = 0; hrow < 2; hrow++) {
                int m = mA + hrow * 8;
                float v0 = a4[hrow * 2 + 0], v1 = a4[hrow * 2 + 1];
                if (EPI == 0) {
                    float di = g_dinv[k * NNODE + m];
                    float o0 = di * (v0 + b1[k * 256 + nA]);
                    float o1 = di * (v1 + b1[k * 256 + nA + 1]);
                    *(float2*)&g_ys[k * NM + m * 256 + nA] = make_float2(o0, o1);
                    g_ysT[k * NM + nA * NNODE + m] = o0;
                    g_ysT[k * NM + (nA + 1) * NNODE + m] = o1;
                } else if (EPI == 1) {
                    float o0 = v0 + b1[k * G4 + nA] + b2[k * G4 + nA];
                    float o1 = v1 + b1[k * G4 + nA + 1] + b2[k * G4 + nA + 1];
                    *(float2*)&g_gx[k * NG + m * NOUT + nA] = make_float2(o0, o1);
                } else if (EPI == 2) {
                    float2 gx = *(const float2*)&g_gx[k * NG + m * NOUT + nA];
                    *(float2*)&g_gates[k * NG + m * NOUT + nA] =
                        make_float2(v0 + gx.x, v1 + gx.y);
                } else {
                    float d0 = tanhf(v0 + b1[k * 256 + nA]);
                    float d1 = tanhf(v1 + b1[k * 256 + nA + 1]);
                    *(float2*)&g_delta[k * NM + m * 256 + nA] = make_float2(d0, d1);
                    float z0 = xin[m * 256 + nA] + d0;
                    float z1 = xin[m * 256 + nA + 1] + d1;
                    if (nA >= SIG_LO && nA < SIG_HI) z0 = sigf(z0);
                    if (nA + 1 >= SIG_LO && nA + 1 < SIG_HI) z1 = sigf(z1);
                    outp[(m * 256 + nA) * NK + k] = z0;
                    outp[(m * 256 + nA + 1) * NK + k] = z1;
                }
            }
        }
    }
}

// ---------------- SpMM: C[m][n] = sum_j bit(m,j) * ysT[n][j]; K=4096 --------
__global__ void __launch_bounds__(256, 2) spmm_mma()
{
    __shared__ float As[128][36];
    __shared__ float Bs[128][36];

    int tid = threadIdx.x;
    int lane = tid & 31, wid = tid >> 5;
    int wm = wid & 3, wn = wid >> 2;
    int g = lane >> 2, t = lane & 3;
    int k = blockIdx.z;
    int m0 = blockIdx.y * 128, n0 = blockIdx.x * 128;

    const unsigned* bitsk = g_bits + (size_t)k * NNODE * NWRD;
    const float* ysT = g_ysT + k * NM;

    float acc[2][8][4] = {};

    for (int kt = 0; kt < NNODE; kt += 32) {
        int wordi = kt >> 5;
        #pragma unroll
        for (int u = 0; u < 4; u++) {
            int idx = tid + u * 256;
            int row = idx >> 3, s = idx & 7;
            unsigned w = bitsk[(m0 + row) * NWRD + wordi];
            int sh = s * 4;
            float4 v;
            v.x = (w >> (sh + 0)) & 1u ? 1.f : 0.f;
            v.y = (w >> (sh + 1)) & 1u ? 1.f : 0.f;
            v.z = (w >> (sh + 2)) & 1u ? 1.f : 0.f;
            v.w = (w >> (sh + 3)) & 1u ? 1.f : 0.f;
            *(float4*)&As[row][sh] = v;
        }
        #pragma unroll
        for (int u = 0; u < 4; u++) {
            int idx = tid + u * 256;
            int row = idx >> 3, c4 = (idx & 7) << 2;
            *(float4*)&Bs[row][c4] = *(const float4*)(ysT + (n0 + row) * NNODE + kt + c4);
        }
        __syncthreads();
        #pragma unroll
        for (int kk = 0; kk < 4; kk++) {
            int k0 = kk * 8;
            uint32_t af[2][4];
            #pragma unroll
            for (int mt = 0; mt < 2; mt++) {
                int r = wm * 32 + mt * 16 + g;
                af[mt][0] = __float_as_uint(As[r][k0 + t]);
                af[mt][1] = __float_as_uint(As[r + 8][k0 + t]);
                af[mt][2] = __float_as_uint(As[r][k0 + t + 4]);
                af[mt][3] = __float_as_uint(As[r + 8][k0 + t + 4]);
            }
            #pragma unroll
            for (int nt = 0; nt < 8; nt++) {
                int cN = wn * 64 + nt * 8 + g;
                uint32_t b0 = __float_as_uint(Bs[cN][k0 + t]);
                uint32_t b1v = __float_as_uint(Bs[cN][k0 + t + 4]);
                mma8(acc[0][nt], af[0], b0, b1v);
                mma8(acc[1][nt], af[1], b0, b1v);
            }
        }
        __syncthreads();
    }

    #pragma unroll
    for (int mt = 0; mt < 2; mt++) {
        #pragma unroll
        for (int nt = 0; nt < 8; nt++) {
            int mA = m0 + wm * 32 + mt * 16 + g;
            int nA = n0 + wn * 64 + nt * 8 + 2 * t;
            float* a4 = acc[mt][nt];
            #pragma unroll
            for (int hrow = 0; hrow < 2; hrow++) {
                int m = mA + hrow * 8;
                float di = g_dinv[k * NNODE + m];
                float2 s0 = *(const float2*)&g_ys[k * NM + m * 256 + nA];
                float o0 = di * (a4[hrow * 2 + 0] + s0.x);
                float o1 = di * (a4[hrow * 2 + 1] + s0.y);
                *(float2*)&g_gnn[k * NM + m * 256 + nA] = make_float2(o0, o1);
            }
        }
    }
}

// ---------------- LSTM elementwise (batched over k) -------------------------
__global__ void lstm_elem(int first)
{
    int idx = blockIdx.x * 256 + threadIdx.x;       // < NK*NM
    int k = idx >> 20;
    int r = idx & (NM - 1);
    int n = r >> 8, hh = r & 255;
    const float* gp = (first ? g_gx : g_gates) + k * NG + n * G4 + hh;
    float gi = gp[0], gf = gp[256], gg = gp[512], go = gp[768];
    float cp = first ? 0.f : g_c[idx];
    float cn = sigf(gf) * cp + sigf(gi) * tanhf(gg);
    g_c[idx] = cn;
    g_h[idx] = sigf(go) * tanhf(cn);
}

// ---------------- final prediction ------------------------------------------
__global__ void final_kernel(const float* __restrict__ x, float* __restrict__ out)
{
    int idx = blockIdx.x * 256 + threadIdx.x;       // < NM
    int f = idx & 255;
    float d = (g_delta[idx] + g_delta[idx + NM] + g_delta[idx + 2 * NM]) * (1.f / 3.f);
    float z = x[idx] + d;
    if (f >= SIG_LO && f < SIG_HI) z = sigf(z);
    out[idx] = z;
}

// ---------------- launcher ---------------------------------------------------
extern "C" void kernel_launch(void* const* d_in, const int* in_sizes, int n_in,
                              void* d_out, int out_size)
{
    (void)in_sizes; (void)n_in; (void)out_size;
    const float* x     = (const float*)d_in[0];
    const float* gnn_w = (const float*)d_in[1];
    const float* gnn_b = (const float*)d_in[2];
    const float* w_ih  = (const float*)d_in[3];
    const float* w_hh  = (const float*)d_in[4];
    const float* b_ih  = (const float*)d_in[5];
    const float* b_hh  = (const float*)d_in[6];
    const float* fc_w  = (const float*)d_in[7];
    const float* fc_b  = (const float*)d_in[8];
    const int*   adj   = (const int*)d_in[9];
    float* out = (float*)d_out;

    // adj pass: degrees + bitmasks + adj->float copy into out
    prep_kernel<<<NNODE, 256>>>(adj, out + AOFF);

    // gnn_w [K][F][H] -> g_gwt [K][H][F]
    transpose_w<<<dim3(8, 8, 3), dim3(32, 8)>>>(gnn_w);

    // ys = dinv .* (x @ gnn_w + gnn_b)  (+ fused transpose -> g_ysT)
    gemm_mma<0><<<dim3(2, 32, 3), 256>>>(x, nullptr, gnn_b, nullptr, nullptr, nullptr);

    // gnn = dinv .* (A_bits @ ys + ys)
    spmm_mma<<<dim3(2, 32, 3), 256>>>();

    // gx = gnn @ w_ih^T + b_ih + b_hh
    gemm_mma<1><<<dim3(8, 32, 3), 256>>>(nullptr, w_ih, b_ih, b_hh, nullptr, nullptr);

    // LSTM step 1 (h=c=0): gates == gx
    lstm_elem<<<NK * NM / 256, 256>>>(1);

    // LSTM steps 2..5
    for (int step = 1; step < 5; step++) {
        gemm_mma<2><<<dim3(8, 32, 3), 256>>>(nullptr, w_hh, nullptr, nullptr, nullptr, nullptr);
        lstm_elem<<<NK * NM / 256, 256>>>(0);
    }

    // delta/fc + zbar
    gemm_mma<3><<<dim3(2, 32, 3), 256>>>(nullptr, fc_w, fc_b, nullptr, x, out + ZOFF);

    // pred = sig_slice(x + mean(deltas))
    final_kernel<<<NM / 256, 256>>>(x, out);
}

// round 5
// speedup vs baseline: 3.1335x; 1.2253x over previous
#include <cuda_runtime.h>
#include <math.h>
#include <stdint.h>

// ---------------- problem constants ----------------
constexpr int NNODE = 4096;
constexpr int FD    = 256;
constexpr int NK    = 3;
constexpr int G4    = 1024;
constexpr int NWRD  = 128;
constexpr int SIG_LO = 10;
constexpr int SIG_HI = 253;
constexpr int NM = NNODE * FD;      // 2^20
constexpr int NG = NNODE * G4;
constexpr int ZOFF = NM;
constexpr int AOFF = ZOFF + NM * NK;

// ---------------- scratch (device globals) ----------------
__device__ float g_ys  [NK * NM];       // [k][m][256]
__device__ float g_ysT [NK * NM];       // [k][n][4096]
__device__ float g_gnnT[NK * NM];       // [k][n][4096]
__device__ float g_gx  [NK * NG];       // [k][m][1024] (kernel-native permuted n)
__device__ float g_hT0 [NK * NM];       // [k][u][4096]
__device__ float g_hT1 [NK * NM];
__device__ float g_cT  [NK * NM];
__device__ float g_delta[NK * NM];      // [k][m][256]
__device__ float g_bsum[NK * G4];
__device__ float g_dinv[NK * NNODE];
__device__ unsigned g_bits[NK * NNODE * NWRD];

__device__ __forceinline__ float sigf(float x) { return 1.f / (1.f + expf(-x)); }

__device__ __forceinline__ uint32_t smem_u32(const void* p) {
    uint32_t a;
    asm("{ .reg .u64 t; cvta.to.shared.u64 t, %1; cvt.u32.u64 %0, t; }" : "=r"(a) : "l"(p));
    return a;
}
__device__ __forceinline__ void cp_async16(uint32_t dst, const void* src) {
    asm volatile("cp.async.cg.shared.global [%0], [%1], 16;" :: "r"(dst), "l"(src) : "memory");
}
__device__ __forceinline__ void cp_async4(uint32_t dst, const void* src) {
    asm volatile("cp.async.ca.shared.global [%0], [%1], 4;" :: "r"(dst), "l"(src) : "memory");
}
#define CP_COMMIT() asm volatile("cp.async.commit_group;" ::: "memory")
#define CP_WAIT1()  asm volatile("cp.async.wait_group 1;" ::: "memory")

// m16n8k8 tf32 mma
__device__ __forceinline__ void mma8(float* c, const uint32_t* a, uint32_t b0, uint32_t b1) {
    asm volatile(
        "mma.sync.aligned.m16n8k8.row.col.f32.tf32.tf32.f32 "
        "{%0,%1,%2,%3}, {%4,%5,%6,%7}, {%8,%9}, {%0,%1,%2,%3};"
        : "+f"(c[0]), "+f"(c[1]), "+f"(c[2]), "+f"(c[3])
        : "r"(a[0]), "r"(a[1]), "r"(a[2]), "r"(a[3]), "r"(b0), "r"(b1));
}

// ---------------- prep: degrees + bit-pack + adj -> float out --------------
__global__ void prep_kernel(const int* __restrict__ adj, float* __restrict__ out_adj)
{
    int i = blockIdx.x;
    int t = threadIdx.x;
    int lane = t & 31, warp = t >> 5;
    int c0 = 0, c1 = 0, c2 = 0;
    for (int w = warp; w < NWRD; w += 8) {
        int j = w * 32 + lane;
        long base = ((long)i * NNODE + j) * 3;
        int a0 = adj[base], a1 = adj[base + 1], a2 = adj[base + 2];
        out_adj[base]     = (float)a0;
        out_adj[base + 1] = (float)a1;
        out_adj[base + 2] = (float)a2;
        unsigned m0 = __ballot_sync(0xffffffffu, a0 != 0);
        unsigned m1 = __ballot_sync(0xffffffffu, a1 != 0);
        unsigned m2 = __ballot_sync(0xffffffffu, a2 != 0);
        if (lane == 0) {
            g_bits[0 * NNODE * NWRD + i * NWRD + w] = m0;
            g_bits[1 * NNODE * NWRD + i * NWRD + w] = m1;
            g_bits[2 * NNODE * NWRD + i * NWRD + w] = m2;
            c0 += __popc(m0); c1 += __popc(m1); c2 += __popc(m2);
        }
    }
    __shared__ int sc[8][3];
    if (lane == 0) { sc[warp][0] = c0; sc[warp][1] = c1; sc[warp][2] = c2; }
    __syncthreads();
    if (t < 3) {
        int s = 0;
        #pragma unroll
        for (int w = 0; w < 8; w++) s += sc[w][t];
        g_dinv[t * NNODE + i] = rsqrtf((float)(s + 1));
    }
}

// ---------------- bsum = b_ih + b_hh ----------------------------------------
__global__ void bsum_kernel(const float* __restrict__ bih, const float* __restrict__ bhh)
{
    int i = blockIdx.x * 256 + threadIdx.x;
    if (i < NK * G4) g_bsum[i] = bih[i] + bhh[i];
}

// ---------------- dense tf32 GEMM, BM=128 BN=128 BK=32, K=256, 2-stage ------
// EPI 0: ys   A=x(row), B=gnn_w(col)       : ys = dinv*(acc+gnn_b); + ysT
// EPI 1: gx   A=gnnT(col), B=w_ih(rowperm) : gx = acc+bsum; LSTM step1 -> hT,cT
// EPI 2: step A=hT(col),  B=w_hh(rowperm)  : gates = acc+gx; LSTM -> hT,cT
// EPI 3: fc   A=hT(col),  B=fc_w(row)      : delta=tanh(acc+fc_b); zbar
template <int EPI>
__global__ void __launch_bounds__(256, 2) gemm_mma(
    const float* __restrict__ Ap, const float* __restrict__ Bp,
    const float* __restrict__ b1, const float* __restrict__ xin,
    float* __restrict__ outp, float* __restrict__ hTout)
{
    constexpr bool ACOL  = (EPI != 0);
    constexpr bool BCOL  = (EPI == 0);
    constexpr bool BPERM = (EPI == 1 || EPI == 2);
    constexpr int NT = 8;               // 256 / 32
    constexpr int SD = 4608;            // floats per stage (max of 128*36, 32*136)

    extern __shared__ float sm[];
    uint32_t sA = smem_u32(sm);
    uint32_t sB = sA + 2 * SD * 4;

    int tid = threadIdx.x, lane = tid & 31, wid = tid >> 5;
    int wm = wid & 3, wn = wid >> 2;
    int g = lane >> 2, t = lane & 3;
    int k = blockIdx.z;
    int m0 = blockIdx.y * 128, n0 = blockIdx.x * 128;
    int h0 = n0 >> 2;

    const float* Ab = ACOL ? (Ap + k * NM + m0) : (Ap + m0 * 256);
    const float* Bb;
    if (BCOL)       Bb = Bp + k * 65536;
    else if (BPERM) Bb = Bp + k * G4 * 256;
    else            Bb = Bp + k * 65536;

    auto load_stage = [&](int ct, int s) {
        int kt = ct * 32;
        if (ACOL) {
            // 32 rows (k) x 128 cols (m): 1024 float4s
            #pragma unroll
            for (int u = 0; u < 4; u++) {
                int idx = tid + u * 256;
                int r = idx >> 5, cm = (idx & 31) * 4;
                cp_async16(sA + (s * SD + r * 136 + cm) * 4, Ab + (kt + r) * NNODE + cm);
            }
        } else {
            #pragma unroll
            for (int u = 0; u < 4; u++) {
                int idx = tid + u * 256;
                int row = idx >> 3, c4 = (idx & 7) * 4;
                cp_async16(sA + (s * SD + row * 36 + c4) * 4, Ab + row * 256 + kt + c4);
            }
        }
        if (BCOL) {
            // 32 rows (k) x 128 cols (n): 1024 float4s
            #pragma unroll
            for (int u = 0; u < 4; u++) {
                int idx = tid + u * 256;
                int r = idx >> 5, cm = (idx & 31) * 4;
                cp_async16(sB + (s * SD + r * 136 + cm) * 4, Bb + (kt + r) * 256 + n0 + cm);
            }
        } else {
            #pragma unroll
            for (int u = 0; u < 4; u++) {
                int idx = tid + u * 256;
                int row = idx >> 3, c4 = (idx & 7) * 4;
                int brow;
                if (BPERM) brow = ((row >> 4) & 3) * 256 + h0 + (row >> 6) * 16 + (row & 15);
                else       brow = n0 + row;
                cp_async16(sB + (s * SD + row * 36 + c4) * 4, Bb + brow * 256 + kt + c4);
            }
        }
    };

    float acc[2][8][4] = {};

    load_stage(0, 0); CP_COMMIT();
    for (int c = 0; c < NT; c++) {
        int s = c & 1;
        if (c + 1 < NT) load_stage(c + 1, (c + 1) & 1);
        CP_COMMIT();
        CP_WAIT1();
        __syncthreads();
        const float* Asl = sm + s * SD;
        const float* Bsl = sm + 2 * SD + s * SD;
        #pragma unroll
        for (int kk = 0; kk < 4; kk++) {
            int k0 = kk * 8;
            uint32_t af[2][4];
            #pragma unroll
            for (int mt = 0; mt < 2; mt++) {
                int r = wm * 32 + mt * 16 + g;
                if (ACOL) {
                    af[mt][0] = __float_as_uint(Asl[(k0 + t) * 136 + r]);
                    af[mt][1] = __float_as_uint(Asl[(k0 + t) * 136 + r + 8]);
                    af[mt][2] = __float_as_uint(Asl[(k0 + t + 4) * 136 + r]);
                    af[mt][3] = __float_as_uint(Asl[(k0 + t + 4) * 136 + r + 8]);
                } else {
                    af[mt][0] = __float_as_uint(Asl[r * 36 + k0 + t]);
                    af[mt][1] = __float_as_uint(Asl[(r + 8) * 36 + k0 + t]);
                    af[mt][2] = __float_as_uint(Asl[r * 36 + k0 + t + 4]);
                    af[mt][3] = __float_as_uint(Asl[(r + 8) * 36 + k0 + t + 4]);
                }
            }
            #pragma unroll
            for (int nt = 0; nt < 8; nt++) {
                int cN = wn * 64 + nt * 8 + g;
                uint32_t b0, b1v;
                if (BCOL) {
                    b0  = __float_as_uint(Bsl[(k0 + t) * 136 + cN]);
                    b1v = __float_as_uint(Bsl[(k0 + t + 4) * 136 + cN]);
                } else {
                    b0  = __float_as_uint(Bsl[cN * 36 + k0 + t]);
                    b1v = __float_as_uint(Bsl[cN * 36 + k0 + t + 4]);
                }
                mma8(acc[0][nt], af[0], b0, b1v);
                mma8(acc[1][nt], af[1], b0, b1v);
            }
        }
        __syncthreads();
    }

    // ---------------- epilogues ----------------
    if (EPI == 0) {
        #pragma unroll
        for (int mt = 0; mt < 2; mt++) {
            #pragma unroll
            for (int hrow = 0; hrow < 2; hrow++) {
                int m = m0 + wm * 32 + mt * 16 + hrow * 8 + g;
                float di = g_dinv[k * NNODE + m];
                #pragma unroll
                for (int nt = 0; nt < 8; nt++) {
                    int nA = n0 + wn * 64 + nt * 8 + 2 * t;
                    float o0 = di * (acc[mt][nt][hrow * 2 + 0] + b1[k * 256 + nA]);
                    float o1 = di * (acc[mt][nt][hrow * 2 + 1] + b1[k * 256 + nA + 1]);
                    *(float2*)&g_ys[k * NM + m * 256 + nA] = make_float2(o0, o1);
                    g_ysT[k * NM + nA * NNODE + m] = o0;
                    g_ysT[k * NM + (nA + 1) * NNODE + m] = o1;
                }
            }
        }
    } else if (EPI == 1 || EPI == 2) {
        // add bias (EPI1) or gx (EPI2); EPI1 also stores gx
        #pragma unroll
        for (int mt = 0; mt < 2; mt++) {
            #pragma unroll
            for (int nt = 0; nt < 8; nt++) {
                int gate = nt >> 1, p = nt & 1;
                #pragma unroll
                for (int hrow = 0; hrow < 2; hrow++) {
                    int m = m0 + wm * 32 + mt * 16 + hrow * 8 + g;
                    int pn = n0 + wn * 64 + nt * 8 + 2 * t;
                    float v0, v1;
                    if (EPI == 1) {
                        int bb = k * G4 + gate * 256 + h0 + wn * 16 + p * 8 + 2 * t;
                        v0 = acc[mt][nt][hrow * 2 + 0] + g_bsum[bb];
                        v1 = acc[mt][nt][hrow * 2 + 1] + g_bsum[bb + 1];
                        *(float2*)&g_gx[k * NG + m * 1024 + pn] = make_float2(v0, v1);
                    } else {
                        float2 gx = *(const float2*)&g_gx[k * NG + m * 1024 + pn];
                        v0 = acc[mt][nt][hrow * 2 + 0] + gx.x;
                        v1 = acc[mt][nt][hrow * 2 + 1] + gx.y;
                    }
                    acc[mt][nt][hrow * 2 + 0] = v0;
                    acc[mt][nt][hrow * 2 + 1] = v1;
                }
            }
        }
        // LSTM pointwise in registers (thread owns i/f/g/o quads)
        #pragma unroll
        for (int mt = 0; mt < 2; mt++) {
            #pragma unroll
            for (int p = 0; p < 2; p++) {
                #pragma unroll
                for (int hrow = 0; hrow < 2; hrow++) {
                    int m = m0 + wm * 32 + mt * 16 + hrow * 8 + g;
                    #pragma unroll
                    for (int e = 0; e < 2; e++) {
                        float i_ = acc[mt][p + 0][hrow * 2 + e];
                        float f_ = acc[mt][p + 2][hrow * 2 + e];
                        float gg = acc[mt][p + 4][hrow * 2 + e];
                        float o_ = acc[mt][p + 6][hrow * 2 + e];
                        int u = h0 + wn * 16 + p * 8 + 2 * t + e;
                        long idx = (long)k * NM + u * NNODE + m;
                        float cp = (EPI == 1) ? 0.f : g_cT[idx];
                        float cn = sigf(f_) * cp + sigf(i_) * tanhf(gg);
                        g_cT[idx] = cn;
                        hTout[idx] = sigf(o_) * tanhf(cn);
                    }
                }
            }
        }
    } else { // EPI 3
        #pragma unroll
        for (int mt = 0; mt < 2; mt++) {
            #pragma unroll
            for (int hrow = 0; hrow < 2; hrow++) {
                int m = m0 + wm * 32 + mt * 16 + hrow * 8 + g;
                #pragma unroll
                for (int nt = 0; nt < 8; nt++) {
                    int nA = n0 + wn * 64 + nt * 8 + 2 * t;
                    float d0 = tanhf(acc[mt][nt][hrow * 2 + 0] + b1[k * 256 + nA]);
                    float d1 = tanhf(acc[mt][nt][hrow * 2 + 1] + b1[k * 256 + nA + 1]);
                    *(float2*)&g_delta[k * NM + m * 256 + nA] = make_float2(d0, d1);
                    float z0 = xin[m * 256 + nA] + d0;
                    float z1 = xin[m * 256 + nA + 1] + d1;
                    if (nA >= SIG_LO && nA < SIG_HI) z0 = sigf(z0);
                    if (nA + 1 >= SIG_LO && nA + 1 < SIG_HI) z1 = sigf(z1);
                    outp[(m * 256 + nA) * NK + k] = z0;
                    outp[(m * 256 + nA + 1) * NK + k] = z1;
                }
            }
        }
    }
}

// ---------------- SpMM: bits(A) x ysT(B), K=4096, 2-stage cp.async ----------
__global__ void __launch_bounds__(256, 2) spmm_mma()
{
    constexpr int BSZ = 128 * 36;
    __shared__ float Bs[2][BSZ];
    __shared__ unsigned Wd[2][128];

    uint32_t sBu = smem_u32(&Bs[0][0]);
    uint32_t sWu = smem_u32(&Wd[0][0]);

    int tid = threadIdx.x, lane = tid & 31, wid = tid >> 5;
    int wm = wid & 3, wn = wid >> 2;
    int g = lane >> 2, t = lane & 3;
    int k = blockIdx.z;
    int m0 = blockIdx.y * 128, n0 = blockIdx.x * 128;

    const unsigned* bitsk = g_bits + (size_t)k * NNODE * NWRD;
    const float* ysT = g_ysT + k * NM;

    auto load_stage = [&](int ct, int s) {
        int kt = ct * 32;
        #pragma unroll
        for (int u = 0; u < 4; u++) {
            int idx = tid + u * 256;
            int row = idx >> 3, c4 = (idx & 7) * 4;
            cp_async16(sBu + (s * BSZ + row * 36 + c4) * 4,
                       ysT + (n0 + row) * NNODE + kt + c4);
        }
        if (tid < 128)
            cp_async4(sWu + (s * 128 + tid) * 4, bitsk + (m0 + tid) * NWRD + ct);
    };

    float acc[2][8][4] = {};

    load_stage(0, 0); CP_COMMIT();
    for (int c = 0; c < 128; c++) {
        int s = c & 1;
        if (c + 1 < 128) load_stage(c + 1, (c + 1) & 1);
        CP_COMMIT();
        CP_WAIT1();
        __syncthreads();
        unsigned w00 = Wd[s][wm * 32 + g];
        unsigned w01 = Wd[s][wm * 32 + 8 + g];
        unsigned w10 = Wd[s][wm * 32 + 16 + g];
        unsigned w11 = Wd[s][wm * 32 + 24 + g];
        const float* Bsl = Bs[s];
        #pragma unroll
        for (int kk = 0; kk < 4; kk++) {
            int k0 = kk * 8;
            uint32_t af[2][4];
            af[0][0] = ((w00 >> (k0 + t)) & 1u) * 0x3f800000u;
            af[0][1] = ((w01 >> (k0 + t)) & 1u) * 0x3f800000u;
            af[0][2] = ((w00 >> (k0 + t + 4)) & 1u) * 0x3f800000u;
            af[0][3] = ((w01 >> (k0 + t + 4)) & 1u) * 0x3f800000u;
            af[1][0] = ((w10 >> (k0 + t)) & 1u) * 0x3f800000u;
            af[1][1] = ((w11 >> (k0 + t)) & 1u) * 0x3f800000u;
            af[1][2] = ((w10 >> (k0 + t + 4)) & 1u) * 0x3f800000u;
            af[1][3] = ((w11 >> (k0 + t + 4)) & 1u) * 0x3f800000u;
            #pragma unroll
            for (int nt = 0; nt < 8; nt++) {
                int cN = wn * 64 + nt * 8 + g;
                uint32_t b0  = __float_as_uint(Bsl[cN * 36 + k0 + t]);
                uint32_t b1v = __float_as_uint(Bsl[cN * 36 + k0 + t + 4]);
                mma8(acc[0][nt], af[0], b0, b1v);
                mma8(acc[1][nt], af[1], b0, b1v);
            }
        }
        __syncthreads();
    }

    #pragma unroll
    for (int mt = 0; mt < 2; mt++) {
        #pragma unroll
        for (int hrow = 0; hrow < 2; hrow++) {
            int m = m0 + wm * 32 + mt * 16 + hrow * 8 + g;
            float di = g_dinv[k * NNODE + m];
            #pragma unroll
            for (int nt = 0; nt < 8; nt++) {
                int nA = n0 + wn * 64 + nt * 8 + 2 * t;
                float2 s0 = *(const float2*)&g_ys[k * NM + m * 256 + nA];
                float o0 = di * (acc[mt][nt][hrow * 2 + 0] + s0.x);
                float o1 = di * (acc[mt][nt][hrow * 2 + 1] + s0.y);
                g_gnnT[k * NM + nA * NNODE + m] = o0;
                g_gnnT[k * NM + (nA + 1) * NNODE + m] = o1;
            }
        }
    }
}

// ---------------- final prediction ------------------------------------------
__global__ void final_kernel(const float* __restrict__ x, float* __restrict__ out)
{
    int idx = blockIdx.x * 256 + threadIdx.x;
    int f = idx & 255;
    float d = (g_delta[idx] + g_delta[idx + NM] + g_delta[idx + 2 * NM]) * (1.f / 3.f);
    float z = x[idx] + d;
    if (f >= SIG_LO && f < SIG_HI) z = sigf(z);
    out[idx] = z;
}

// ---------------- launcher ---------------------------------------------------
extern "C" void kernel_launch(void* const* d_in, const int* in_sizes, int n_in,
                              void* d_out, int out_size)
{
    (void)in_sizes; (void)n_in; (void)out_size;
    const float* x     = (const float*)d_in[0];
    const float* gnn_w = (const float*)d_in[1];
    const float* gnn_b = (const float*)d_in[2];
    const float* w_ih  = (const float*)d_in[3];
    const float* w_hh  = (const float*)d_in[4];
    const float* b_ih  = (const float*)d_in[5];
    const float* b_hh  = (const float*)d_in[6];
    const float* fc_w  = (const float*)d_in[7];
    const float* fc_b  = (const float*)d_in[8];
    const int*   adj   = (const int*)d_in[9];
    float* out = (float*)d_out;

    constexpr int DSMEM = 2 * 2 * 4608 * 4;   // 73728 B

    cudaFuncSetAttribute((const void*)gemm_mma<0>, cudaFuncAttributeMaxDynamicSharedMemorySize, DSMEM);
    cudaFuncSetAttribute((const void*)gemm_mma<1>, cudaFuncAttributeMaxDynamicSharedMemorySize, DSMEM);
    cudaFuncSetAttribute((const void*)gemm_mma<2>, cudaFuncAttributeMaxDynamicSharedMemorySize, DSMEM);
    cudaFuncSetAttribute((const void*)gemm_mma<3>, cudaFuncAttributeMaxDynamicSharedMemorySize, DSMEM);

    float *p_gnnT, *p_hT0, *p_hT1;
    cudaGetSymbolAddress((void**)&p_gnnT, g_gnnT);
    cudaGetSymbolAddress((void**)&p_hT0,  g_hT0);
    cudaGetSymbolAddress((void**)&p_hT1,  g_hT1);

    // adj pass: degrees + bitmasks + adj->float copy into out
    prep_kernel<<<NNODE, 256>>>(adj, out + AOFF);
    bsum_kernel<<<(NK * G4 + 255) / 256, 256>>>(b_ih, b_hh);

    // ys = dinv .* (x @ gnn_w + gnn_b)  -> g_ys, g_ysT
    gemm_mma<0><<<dim3(2, 32, 3), 256, DSMEM>>>(x, gnn_w, gnn_b, nullptr, nullptr, nullptr);

    // gnnT = transpose( dinv .* (A_bits @ ys + ys) )
    spmm_mma<<<dim3(2, 32, 3), 256>>>();

    // gx = gnn @ w_ih^T + b; fused LSTM step 1 -> hT0, cT
    gemm_mma<1><<<dim3(8, 32, 3), 256, DSMEM>>>(p_gnnT, w_ih, nullptr, nullptr, nullptr, p_hT0);

    // LSTM steps 2..5 (ping-pong hT buffers)
    gemm_mma<2><<<dim3(8, 32, 3), 256, DSMEM>>>(p_hT0, w_hh, nullptr, nullptr, nullptr, p_hT1);
    gemm_mma<2><<<dim3(8, 32, 3), 256, DSMEM>>>(p_hT1, w_hh, nullptr, nullptr, nullptr, p_hT0);
    gemm_mma<2><<<dim3(8, 32, 3), 256, DSMEM>>>(p_hT0, w_hh, nullptr, nullptr, nullptr, p_hT1);
    gemm_mma<2><<<dim3(8, 32, 3), 256, DSMEM>>>(p_hT1, w_hh, nullptr, nullptr, nullptr, p_hT0);

    // delta = tanh(h @ fc_w^T + fc_b); zbar
    gemm_mma<3><<<dim3(2, 32, 3), 256, DSMEM>>>(p_hT0, fc_w, fc_b, x, out + ZOFF, nullptr);

    // pred = sig_slice(x + mean(deltas))
    final_kernel<<<NM / 256, 256>>>(x, out);
}